// round 14
// baseline (speedup 1.0000x reference)
#include <cuda_runtime.h>
#include <cstdint>

#define BB 16
#define NN 4096
#define CC 64
#define SS 1024
#define KK 32
#define MM (BB*SS*KK)   /* 524288 */

// ---------------- scratch (device globals; no runtime allocation) ----------
__device__ float g_newxyz[BB*SS*3];
__device__ float g_F1[BB*NN*64];              // [b][n][o], o contiguous (16.7 MB)
__device__ float g_y0[(size_t)64*MM];         // pre-BN layer0 out [c][m]
__device__ float g_y1[(size_t)64*MM];         // pre-BN layer1 out
__device__ float g_pmax[(size_t)128*16384];   // layer2 pre-BN max over k, [o][b*s]
__device__ float g_pmin[(size_t)128*16384];   // layer2 pre-BN min over k
__device__ float g_stats[3][256];             // per layer: [ch*2]={sum,sumsq}
__device__ float g_scale[3][128];
__device__ float g_shift[3][128];
__device__ int   g_sync[16];                  // FPS progress counter per batch
__device__ int   g_f1done;                    // completed f1 blocks

// packed f32x2 helpers (bitwise identical to scalar rn ops, 2 lanes/instr)
__device__ __forceinline__ unsigned long long fma2(unsigned long long a,
                                                   unsigned long long b,
                                                   unsigned long long c)
{
    unsigned long long d;
    asm("fma.rn.f32x2 %0, %1, %2, %3;" : "=l"(d) : "l"(a), "l"(b), "l"(c));
    return d;
}
__device__ __forceinline__ unsigned long long add2(unsigned long long a,
                                                   unsigned long long b)
{
    unsigned long long d;
    asm("add.rn.f32x2 %0, %1, %2;" : "=l"(d) : "l"(a), "l"(b));
    return d;
}
__device__ __forceinline__ unsigned long long mul2(unsigned long long a,
                                                   unsigned long long b)
{
    unsigned long long d;
    asm("mul.rn.f32x2 %0, %1, %2;" : "=l"(d) : "l"(a), "l"(b));
    return d;
}
__device__ __forceinline__ unsigned long long pack2(float lo, float hi)
{
    unsigned long long d;
    asm("mov.b64 %0, {%1, %2};" : "=l"(d) : "f"(lo), "f"(hi));
    return d;
}
__device__ __forceinline__ void unpack2(float& lo, float& hi, unsigned long long v)
{
    asm("mov.b64 {%0, %1}, %2;" : "=f"(lo), "=f"(hi) : "l"(v));
}
__device__ __forceinline__ void st_release(int* p, int v)
{
    asm volatile("st.release.gpu.s32 [%0], %1;" :: "l"(p), "r"(v) : "memory");
}
__device__ __forceinline__ int ld_acquire(const int* p)
{
    int v;
    asm volatile("ld.acquire.gpu.s32 %0, [%1];" : "=r"(v) : "l"(p) : "memory");
    return v;
}

// ---------------- 0) init: zero counters + stats (each graph replay) -------
__global__ void init_kernel()
{
    int t = threadIdx.x;
    for (int i = t; i < 3*256; i += 256) (&g_stats[0][0])[i] = 0.f;
    if (t < 16) g_sync[t] = 0;
    if (t == 16) g_f1done = 0;
}

// ---- 1) mega kernel: FPS (0..15) | f1 (16..527) | ball+assemble (528..) ---
__global__ __launch_bounds__(512) void mega_kernel(const float* __restrict__ xyz,
                                                   const float* __restrict__ feat,
                                                   const float* __restrict__ w0,
                                                   const float* __restrict__ b0,
                                                   float* __restrict__ out_newxyz)
{
    __shared__ float pool[12288];   // 48KB, shared by all roles
    int t = threadIdx.x;

    if (blockIdx.x < 16) {
        // ---------------- FPS role (producer) ----------------
        float4* swc = (float4*)pool;            // [2][32] {x,y,z,keybits}
        int b = blockIdx.x;
        int lane = t & 31, wid = t >> 5;        // wid 0..15
        if (t < 64) swc[t] = make_float4(0.f, 0.f, 0.f, 0.f);  // pads zeroed

        const float* xb = xyz + (size_t)b*NN*3;
        const float4* p = (const float4*)xb + t*6;
        float4 q0=p[0], q1=p[1], q2=p[2], q3=p[3], q4=p[4], q5=p[5];
        float X[8], Y[8], Z[8];
        X[0]=q0.x; Y[0]=q0.y; Z[0]=q0.z;
        X[1]=q0.w; Y[1]=q1.x; Z[1]=q1.y;
        X[2]=q1.z; Y[2]=q1.w; Z[2]=q2.x;
        X[3]=q2.y; Y[3]=q2.z; Z[3]=q2.w;
        X[4]=q3.x; Y[4]=q3.y; Z[4]=q3.z;
        X[5]=q3.w; Y[5]=q4.x; Z[5]=q4.y;
        X[6]=q4.z; Y[6]=q4.w; Z[6]=q5.x;
        X[7]=q5.y; Y[7]=q5.z; Z[7]=q5.w;
        unsigned long long pxP[4], pyP[4], pzP[4];
        #pragma unroll
        for (int g = 0; g < 4; g++) {
            pxP[g] = pack2(X[2*g], X[2*g+1]);
            pyP[g] = pack2(Y[2*g], Y[2*g+1]);
            pzP[g] = pack2(Z[2*g], Z[2*g+1]);
        }
        float d[8];
        #pragma unroll
        for (int j = 0; j < 8; j++) d[j] = 1e10f;

        float cx = xb[0], cy = xb[1], cz = xb[2];
        if (t == 0) {
            float* o  = out_newxyz + (size_t)b*SS*3;
            float* o2 = g_newxyz  + (size_t)b*SS*3;
            o[0]=cx; o[1]=cy; o[2]=cz;
            o2[0]=cx; o2[1]=cy; o2[2]=cz;
            st_release(&g_sync[b], 1);
        }
        __syncthreads();

        for (int it = 0; it < SS-1; ++it) {
            int buf = (it & 1)*32;
            unsigned long long nx = pack2(-cx,-cx);
            unsigned long long ny = pack2(-cy,-cy);
            unsigned long long nz = pack2(-cz,-cz);
            #pragma unroll
            for (int g = 0; g < 4; g++) {
                unsigned long long dx = add2(pxP[g], nx);
                unsigned long long dy = add2(pyP[g], ny);
                unsigned long long dz = add2(pzP[g], nz);
                unsigned long long s  = add2(add2(mul2(dx,dx), mul2(dy,dy)), mul2(dz,dz));
                float e0, e1; unpack2(e0, e1, s);
                d[2*g]   = fminf(d[2*g],   e0);
                d[2*g+1] = fminf(d[2*g+1], e1);
            }
            float m = d[0];
            #pragma unroll
            for (int j = 1; j < 8; j++) m = fmaxf(m, d[j]);
            unsigned bits = __float_as_uint(m);            // d >= 0: order-preserving
            unsigned mb = __reduce_max_sync(0xffffffffu, bits);
            unsigned vot = __ballot_sync(0xffffffffu, bits == mb);
            int winLane = __ffs(vot) - 1;                  // first lane = first index
            if (lane == winLane) {
                int j = 7;                                  // descending: first j wins
                #pragma unroll
                for (int jj = 6; jj >= 0; jj--) if (d[jj] == m) j = jj;
                float vx = (j==0)?X[0]:(j==1)?X[1]:(j==2)?X[2]:(j==3)?X[3]
                          :(j==4)?X[4]:(j==5)?X[5]:(j==6)?X[6]:X[7];
                float vy = (j==0)?Y[0]:(j==1)?Y[1]:(j==2)?Y[2]:(j==3)?Y[3]
                          :(j==4)?Y[4]:(j==5)?Y[5]:(j==6)?Y[6]:Y[7];
                float vz = (j==0)?Z[0]:(j==1)?Z[1]:(j==2)?Z[2]:(j==3)?Z[3]
                          :(j==4)?Z[4]:(j==5)?Z[5]:(j==6)?Z[6]:Z[7];
                swc[buf + wid] = make_float4(vx, vy, vz, __uint_as_float(mb));
            }
            __syncthreads();
            float4 cnd = swc[buf + lane];                  // slots 16-31 = zero pads
            unsigned cb = __float_as_uint(cnd.w);
            unsigned mh = __reduce_max_sync(0xffffffffu, cb);
            unsigned v2 = __ballot_sync(0xffffffffu, cb == mh);
            int ws = __ffs(v2) - 1;                        // lowest wid = first index
            float4 c = swc[buf + ws];                      // broadcast LDS
            cx = c.x; cy = c.y; cz = c.z;
            if (t == 0) {
                size_t o = ((size_t)b*SS + it + 1)*3;
                out_newxyz[o]   = c.x; out_newxyz[o+1] = c.y; out_newxyz[o+2] = c.z;
                g_newxyz[o]     = c.x; g_newxyz[o+1]   = c.y; g_newxyz[o+2]   = c.z;
                st_release(&g_sync[b], it + 2);            // centroids 0..it+1 ready
            }
        }
    } else if (blockIdx.x < 528) {
        // ---------------- f1 role: F1 = W0[:,3:67] x features ----------------
        float* Wt = pool;          // [64][64]
        float* Fs = pool + 4096;   // [64][128]
        int bid = blockIdx.x - 16;
        int b = bid >> 5, n0 = (bid & 31)*128;
        for (int i = t; i < 4096; i += 512) {
            int o = i >> 6, c = i & 63;
            Wt[c*64 + o] = w0[o*67 + 3 + c];
        }
        const float* fb = feat + (size_t)b*CC*NN + n0;
        for (int f = t; f < 2048; f += 512) {
            int c = f >> 5, j = f & 31;
            *(float4*)&Fs[c*128 + j*4] = *(const float4*)(fb + (size_t)c*NN + j*4);
        }
        __syncthreads();
        int nl = t >> 4, og = t & 15;
        float acc[4][4];
        #pragma unroll
        for (int r = 0; r < 4; r++) {
            #pragma unroll
            for (int o = 0; o < 4; o++) acc[r][o] = 0.f;
        }
        #pragma unroll 8
        for (int c = 0; c < 64; c++) {
            float4 a = *(float4*)&Fs[c*128 + nl*4];
            float4 w = *(float4*)&Wt[c*64 + og*4];
            float av[4] = {a.x, a.y, a.z, a.w};
            float wv[4] = {w.x, w.y, w.z, w.w};
            #pragma unroll
            for (int r = 0; r < 4; r++)
                #pragma unroll
                for (int o = 0; o < 4; o++) acc[r][o] = fmaf(av[r], wv[o], acc[r][o]);
        }
        float* dst = g_F1 + ((size_t)(b*NN + n0 + nl*4))*64 + og*4;
        #pragma unroll
        for (int r = 0; r < 4; r++) {
            float4 x = {acc[r][0], acc[r][1], acc[r][2], acc[r][3]};
            *(float4*)(dst + (size_t)r*64) = x;
        }
        // publish completion (canonical fence-then-count pattern)
        __threadfence();
        __syncthreads();
        if (t == 0) atomicAdd(&g_f1done, 1);
    } else {
        // -------- ball+assemble role (consumer): 4 centroids = 128 m --------
        if (t >= 256) return;                   // 256-thread logic
        int bid2 = blockIdx.x - 528;            // 0..4095, sgrp-major
        int sgrp = bid2 >> 4, b = bid2 & 15;
        int m0 = b*32768 + sgrp*128;
        int s0 = sgrp*4;

        int*   sn  = (int*)pool;                // [128]
        float* sgx = pool + 128;
        float* sgy = pool + 256;
        float* sgz = pool + 384;
        float (*sF)[65] = (float(*)[65])(pool + 512);   // [128][65]

        // spin until the 4 centroids and all F1 tiles are published
        while (ld_acquire(&g_sync[b]) < s0 + 4) __nanosleep(128);
        while (ld_acquire(&g_f1done) < 512)     __nanosleep(128);

        int wid = t >> 5, lane = t & 31;
        const float* bx = xyz + (size_t)b*NN*3;

        if (wid < 4) {                          // exact ball query, 1 warp/centroid
            int s = s0 + wid;
            const float* ctr = g_newxyz + ((size_t)(b*SS + s))*3;
            float cx = ctr[0], cy = ctr[1], cz = ctr[2];
            int* outp = sn + wid*32;
            int cnt = 0, first = 0; bool has = false;
            for (int n0 = 0; n0 < NN; n0 += 32) {
                int n = n0 + lane;
                float x = bx[n*3+0], y = bx[n*3+1], z = bx[n*3+2];
                float dx = __fsub_rn(cx, x), dy = __fsub_rn(cy, y), dz = __fsub_rn(cz, z);
                float d2 = __fadd_rn(__fadd_rn(__fmul_rn(dx,dx), __fmul_rn(dy,dy)), __fmul_rn(dz,dz));
                bool in = d2 < 0.04f;
                unsigned bal = __ballot_sync(0xffffffffu, in);
                if (cnt == 0 && bal) { first = n0 + __ffs(bal) - 1; has = true; }
                if (in) {
                    int pos = cnt + __popc(bal & ((1u << lane) - 1u));
                    if (pos < KK) outp[pos] = n;
                }
                cnt += __popc(bal);
                if (cnt >= KK) break;
            }
            if (cnt < KK) {
                int fill = has ? first : 0;
                int p = cnt + lane;
                if (p < KK) outp[p] = fill;
            }
        }
        __syncthreads();

        if (t < 128) {
            int s = s0 + (t >> 5);
            int n = sn[t];
            const float* c = g_newxyz + ((size_t)(b*SS + s))*3;
            const float* p = bx + (size_t)n*3;
            sgx[t] = __fsub_rn(p[0], c[0]);
            sgy[t] = __fsub_rn(p[1], c[1]);
            sgz[t] = __fsub_rn(p[2], c[2]);
        }
        __syncthreads();
        {
            int ml = t >> 1, half = t & 1;
            int n = sn[ml];
            const float* src = g_F1 + ((size_t)(b*NN + n))*64 + half*32;
            #pragma unroll
            for (int i = 0; i < 8; i++) {
                float4 v = *(const float4*)(src + i*4);
                float* dd = &sF[ml][half*32 + i*4];
                dd[0] = v.x; dd[1] = v.y; dd[2] = v.z; dd[3] = v.w;
            }
        }
        __syncthreads();
        int o = t >> 2, q = t & 3;
        float wx = w0[o*67+0], wy = w0[o*67+1], wz = w0[o*67+2], bb = b0[o];
        float s1 = 0.f, s2 = 0.f;
        #pragma unroll 8
        for (int i = 0; i < 32; i++) {
            int ml = i*4 + q;
            float v = sF[ml][o] + sgx[ml]*wx + sgy[ml]*wy + sgz[ml]*wz + bb;
            sF[ml][o] = v;
            s1 += v; s2 = fmaf(v, v, s2);
        }
        s1 += __shfl_down_sync(0xffffffffu, s1, 2, 4);
        s1 += __shfl_down_sync(0xffffffffu, s1, 1, 4);
        s2 += __shfl_down_sync(0xffffffffu, s2, 2, 4);
        s2 += __shfl_down_sync(0xffffffffu, s2, 1, 4);
        if (q == 0) {
            atomicAdd(&g_stats[0][o*2],   s1);
            atomicAdd(&g_stats[0][o*2+1], s2);
        }
        __syncthreads();
        int w = t >> 5, lane2 = t & 31;
        #pragma unroll
        for (int oo = 0; oo < 8; oo++) {
            int o2 = w*8 + oo;
            float4 v = { sF[lane2*4+0][o2], sF[lane2*4+1][o2],
                         sF[lane2*4+2][o2], sF[lane2*4+3][o2] };
            *(float4*)(g_y0 + (size_t)o2*MM + m0 + lane2*4) = v;
        }
    }
}

// ---------------- BN finalize: scale/shift from stats ----------------------
__global__ void finalize_kernel(const float* __restrict__ g, const float* __restrict__ be,
                                int layer, int cout)
{
    int o = threadIdx.x;
    if (o < cout) {
        float inv  = 1.0f / (float)MM;
        float mean = g_stats[layer][o*2]   * inv;
        float ex2  = g_stats[layer][o*2+1] * inv;
        float var  = fmaxf(ex2 - mean*mean, 0.f);
        float sc   = g[o] * rsqrtf(var + 1e-5f);
        g_scale[layer][o] = sc;
        g_shift[layer][o] = be[o] - sc*mean;
    }
}

// --- GEMM v2c (R11-proven): m256/o64, K 2x32, swizzled Xs, 2 CTAs/SM -------
template<int L, int OT>
__global__ __launch_bounds__(256, 2) void gemm_kernel(const float* __restrict__ W,
                                                      const float* __restrict__ bias)
{
    __shared__ unsigned long long Wd[32][64];   // dup pairs, 16KB (32c x 64o)
    __shared__ float Xs[32][256];               // 32KB (32c x 256m), XOR-swizzled

    const float* X = (L == 1) ? g_y0 : g_y1;
    const int scL = L - 1, stL = L;

    int m0 = blockIdx.x*256, t = threadIdx.x;
    int wid = t >> 5, lane = t & 31;
    int o0 = wid*8;            // warp-uniform o fragment (broadcast LDS)
    int mB = lane*8;           // logical per-lane m fragment (8 floats)
    int off0 = lane*32;        off0 ^= ((off0 >> 3) & 16);
    int off1 = lane*32 + 16;   off1 ^= ((off1 >> 3) & 16);

    for (int ot = 0; ot < OT; ot++) {
        int oB = ot*64;
        unsigned long long acc[8][4];
        #pragma unroll
        for (int o = 0; o < 8; o++) {
            #pragma unroll
            for (int p = 0; p < 4; p++) acc[o][p] = 0ull;
        }

        #pragma unroll
        for (int kc = 0; kc < 64; kc += 32) {
            __syncthreads();
            for (int i = t; i < 2048; i += 256) {
                int c = i >> 6, o = i & 63;
                float w = W[(size_t)(oB + o)*64 + kc + c];
                Wd[c][o] = pack2(w, w);
            }
            for (int f = t; f < 2048; f += 256) {
                int c = f >> 6, j = f & 63;
                float4 v = *(const float4*)(X + (size_t)(kc + c)*MM + m0 + j*4);
                float sc = g_scale[scL][kc + c], sh = g_shift[scL][kc + c];
                v.x = fmaxf(fmaf(v.x, sc, sh), 0.f);
                v.y = fmaxf(fmaf(v.y, sc, sh), 0.f);
                v.z = fmaxf(fmaf(v.z, sc, sh), 0.f);
                v.w = fmaxf(fmaf(v.w, sc, sh), 0.f);
                int joff = j*16; joff ^= ((joff >> 3) & 16);
                *(float4*)((char*)&Xs[c][0] + joff) = v;
            }
            __syncthreads();

            #pragma unroll 2
            for (int c = 0; c < 32; c++) {
                const char* rowp = (const char*)&Xs[c][0];
                ulonglong2 b0 = *(const ulonglong2*)(rowp + off0);
                ulonglong2 b1 = *(const ulonglong2*)(rowp + off1);
                unsigned long long bp[4] = {b0.x, b0.y, b1.x, b1.y};
                ulonglong2 a0 = *(const ulonglong2*)&Wd[c][o0];
                ulonglong2 a1 = *(const ulonglong2*)&Wd[c][o0+2];
                ulonglong2 a2 = *(const ulonglong2*)&Wd[c][o0+4];
                ulonglong2 a3 = *(const ulonglong2*)&Wd[c][o0+6];
                unsigned long long ad[8] = {a0.x, a0.y, a1.x, a1.y,
                                            a2.x, a2.y, a3.x, a3.y};
                #pragma unroll
                for (int o = 0; o < 8; o++)
                    #pragma unroll
                    for (int p = 0; p < 4; p++)
                        acc[o][p] = fma2(ad[o], bp[p], acc[o][p]);
            }
        }

        #pragma unroll
        for (int o = 0; o < 8; o++) {
            int og = oB + o0 + o;
            float bb = bias[og];
            float v[8];
            #pragma unroll
            for (int p = 0; p < 4; p++) {
                float lo, hi; unpack2(lo, hi, acc[o][p]);
                v[2*p]   = lo + bb;
                v[2*p+1] = hi + bb;
            }
            if (L == 1) {
                float4 f0 = {v[0], v[1], v[2], v[3]};
                float4 f1 = {v[4], v[5], v[6], v[7]};
                float* dst = g_y1 + (size_t)og*MM + m0 + mB;
                *(float4*)dst       = f0;
                *(float4*)(dst + 4) = f1;
            } else {
                float mx = v[0], mn = v[0];
                #pragma unroll
                for (int i = 1; i < 8; i++) { mx = fmaxf(mx, v[i]); mn = fminf(mn, v[i]); }
                mx = fmaxf(mx, __shfl_down_sync(0xffffffffu, mx, 2, 4));
                mx = fmaxf(mx, __shfl_down_sync(0xffffffffu, mx, 1, 4));
                mn = fminf(mn, __shfl_down_sync(0xffffffffu, mn, 2, 4));
                mn = fminf(mn, __shfl_down_sync(0xffffffffu, mn, 1, 4));
                if ((lane & 3) == 0) {
                    int sg = (m0 >> 5) + (lane >> 2);   // global (b*SS+s)
                    g_pmax[(size_t)og*16384 + sg] = mx;
                    g_pmin[(size_t)og*16384 + sg] = mn;
                }
            }
            float s1 = v[0]+v[1]+v[2]+v[3]+v[4]+v[5]+v[6]+v[7];
            float s2 = v[0]*v[0]+v[1]*v[1]+v[2]*v[2]+v[3]*v[3]
                     + v[4]*v[4]+v[5]*v[5]+v[6]*v[6]+v[7]*v[7];
            #pragma unroll
            for (int off = 16; off; off >>= 1) {
                s1 += __shfl_down_sync(0xffffffffu, s1, off);
                s2 += __shfl_down_sync(0xffffffffu, s2, off);
            }
            if (lane == 0) {
                atomicAdd(&g_stats[stL][og*2],   s1);
                atomicAdd(&g_stats[stL][og*2+1], s2);
            }
        }
    }
}

// --- final: BN2 finalize inline; out = max(relu(a*mx+b), relu(a*mn+b)) -----
__global__ __launch_bounds__(256) void out_kernel(const float* __restrict__ g2,
                                                  const float* __restrict__ be2,
                                                  float* __restrict__ out)
{
    int id = blockIdx.x*256 + threadIdx.x;     // < 128*16384
    int o = id >> 14, sg = id & 16383;
    int b = sg >> 10, s = sg & 1023;
    float inv  = 1.0f / (float)MM;
    float mean = g_stats[2][o*2]   * inv;
    float ex2  = g_stats[2][o*2+1] * inv;
    float var  = fmaxf(ex2 - mean*mean, 0.f);
    float a    = g2[o] * rsqrtf(var + 1e-5f);
    float sh   = be2[o] - a*mean;
    float mx = g_pmax[(size_t)o*16384 + sg];
    float mn = g_pmin[(size_t)o*16384 + sg];
    float v1 = fmaxf(fmaf(mx, a, sh), 0.f);
    float v2 = fmaxf(fmaf(mn, a, sh), 0.f);
    out[((size_t)(b*128 + o))*SS + s] = fmaxf(v1, v2);
}

// ---------------------------------------------------------------------------
extern "C" void kernel_launch(void* const* d_in, const int* in_sizes, int n_in,
                              void* d_out, int out_size)
{
    const float* xyz  = (const float*)d_in[0];
    const float* feat = (const float*)d_in[1];
    const float* w0   = (const float*)d_in[2];
    const float* b0   = (const float*)d_in[3];
    const float* g0   = (const float*)d_in[4];
    const float* be0  = (const float*)d_in[5];
    const float* w1   = (const float*)d_in[6];
    const float* b1   = (const float*)d_in[7];
    const float* g1   = (const float*)d_in[8];
    const float* be1  = (const float*)d_in[9];
    const float* w2   = (const float*)d_in[10];
    const float* b2   = (const float*)d_in[11];
    const float* g2   = (const float*)d_in[12];
    const float* be2  = (const float*)d_in[13];
    float* out = (float*)d_out;

    init_kernel<<<1, 256>>>();                                 // 1: zero sync+stats
    mega_kernel<<<4624, 512>>>(xyz, feat, w0, b0, out);        // 2: fps||f1||ball+asm
    finalize_kernel<<<1, 128>>>(g0, be0, 0, 64);               // 3
    gemm_kernel<1,1><<<2048, 256>>>(w1, b1);                   // 4 <- profiled
    finalize_kernel<<<1, 128>>>(g1, be1, 1, 64);               // 5
    gemm_kernel<2,2><<<2048, 256>>>(w2, b2);                   // 6: pool + stats2
    out_kernel<<<8192, 256>>>(g2, be2, out + (size_t)BB*SS*3); // 7: new_features
}

// round 15
// speedup vs baseline: 3.7788x; 3.7788x over previous
#include <cuda_runtime.h>
#include <cstdint>

#define BB 16
#define NN 4096
#define CC 64
#define SS 1024
#define KK 32
#define MM (BB*SS*KK)   /* 524288 */

// ---------------- scratch (device globals; no runtime allocation) ----------
__device__ float g_newxyz[BB*SS*3];
__device__ int   g_ballidx[MM];
__device__ float g_F1[BB*NN*64];              // [b][n][o], o contiguous (16.7 MB)
__device__ float g_y0[(size_t)64*MM];         // pre-BN layer0 out [c][m]
__device__ float g_y1[(size_t)64*MM];         // pre-BN layer1 out
__device__ float g_pmax[(size_t)128*16384];   // layer2 pre-BN max over k, [o][b*s]
__device__ float g_pmin[(size_t)128*16384];   // layer2 pre-BN min over k
__device__ float g_stats[3][256];             // per layer: [ch*2]={sum,sumsq}
__device__ float g_scale[3][128];
__device__ float g_shift[3][128];

// packed f32x2 helpers (bitwise identical to scalar rn ops, 2 lanes/instr)
__device__ __forceinline__ unsigned long long fma2(unsigned long long a,
                                                   unsigned long long b,
                                                   unsigned long long c)
{
    unsigned long long d;
    asm("fma.rn.f32x2 %0, %1, %2, %3;" : "=l"(d) : "l"(a), "l"(b), "l"(c));
    return d;
}
__device__ __forceinline__ unsigned long long add2(unsigned long long a,
                                                   unsigned long long b)
{
    unsigned long long d;
    asm("add.rn.f32x2 %0, %1, %2;" : "=l"(d) : "l"(a), "l"(b));
    return d;
}
__device__ __forceinline__ unsigned long long mul2(unsigned long long a,
                                                   unsigned long long b)
{
    unsigned long long d;
    asm("mul.rn.f32x2 %0, %1, %2;" : "=l"(d) : "l"(a), "l"(b));
    return d;
}
__device__ __forceinline__ unsigned long long pack2(float lo, float hi)
{
    unsigned long long d;
    asm("mov.b64 %0, {%1, %2};" : "=l"(d) : "f"(lo), "f"(hi));
    return d;
}
__device__ __forceinline__ void unpack2(float& lo, float& hi, unsigned long long v)
{
    asm("mov.b64 {%0, %1}, %2;" : "=f"(lo), "=f"(hi) : "l"(v));
}

// ---- 1) merged: blocks 0..15 = FPS (512thr x 8pts), 16..527 = f1 GEMM -----
//      blocks 16..18 additionally zero g_stats.
__global__ __launch_bounds__(512) void fps_f1_kernel(const float* __restrict__ xyz,
                                                     const float* __restrict__ feat,
                                                     const float* __restrict__ w0,
                                                     float* __restrict__ out_newxyz)
{
    __shared__ float pool[12288];   // 48KB, shared by both roles
    int t = threadIdx.x;

    if (blockIdx.x < 16) {
        // ---------------- FPS role ----------------
        float4* swc = (float4*)pool;            // [2][32] {x,y,z,keybits}
        int b = blockIdx.x;
        int lane = t & 31, wid = t >> 5;        // wid 0..15
        if (t < 64) swc[t] = make_float4(0.f, 0.f, 0.f, 0.f);  // pads zeroed

        const float* xb = xyz + (size_t)b*NN*3;
        const float4* p = (const float4*)xb + t*6;
        float4 q0=p[0], q1=p[1], q2=p[2], q3=p[3], q4=p[4], q5=p[5];
        float X[8], Y[8], Z[8];
        X[0]=q0.x; Y[0]=q0.y; Z[0]=q0.z;
        X[1]=q0.w; Y[1]=q1.x; Z[1]=q1.y;
        X[2]=q1.z; Y[2]=q1.w; Z[2]=q2.x;
        X[3]=q2.y; Y[3]=q2.z; Z[3]=q2.w;
        X[4]=q3.x; Y[4]=q3.y; Z[4]=q3.z;
        X[5]=q3.w; Y[5]=q4.x; Z[5]=q4.y;
        X[6]=q4.z; Y[6]=q4.w; Z[6]=q5.x;
        X[7]=q5.y; Y[7]=q5.z; Z[7]=q5.w;
        unsigned long long pxP[4], pyP[4], pzP[4];
        #pragma unroll
        for (int g = 0; g < 4; g++) {
            pxP[g] = pack2(X[2*g], X[2*g+1]);
            pyP[g] = pack2(Y[2*g], Y[2*g+1]);
            pzP[g] = pack2(Z[2*g], Z[2*g+1]);
        }
        float d[8];
        #pragma unroll
        for (int j = 0; j < 8; j++) d[j] = 1e10f;

        float cx = xb[0], cy = xb[1], cz = xb[2];
        if (t == 0) {
            float* o  = out_newxyz + (size_t)b*SS*3;
            float* o2 = g_newxyz  + (size_t)b*SS*3;
            o[0]=cx; o[1]=cy; o[2]=cz;
            o2[0]=cx; o2[1]=cy; o2[2]=cz;
        }
        __syncthreads();

        for (int it = 0; it < SS-1; ++it) {
            int buf = (it & 1)*32;
            unsigned long long nx = pack2(-cx,-cx);
            unsigned long long ny = pack2(-cy,-cy);
            unsigned long long nz = pack2(-cz,-cz);
            #pragma unroll
            for (int g = 0; g < 4; g++) {
                unsigned long long dx = add2(pxP[g], nx);
                unsigned long long dy = add2(pyP[g], ny);
                unsigned long long dz = add2(pzP[g], nz);
                unsigned long long s  = add2(add2(mul2(dx,dx), mul2(dy,dy)), mul2(dz,dz));
                float e0, e1; unpack2(e0, e1, s);
                d[2*g]   = fminf(d[2*g],   e0);
                d[2*g+1] = fminf(d[2*g+1], e1);
            }
            float m = d[0];
            #pragma unroll
            for (int j = 1; j < 8; j++) m = fmaxf(m, d[j]);
            unsigned bits = __float_as_uint(m);            // d >= 0: order-preserving
            unsigned mb = __reduce_max_sync(0xffffffffu, bits);
            unsigned vot = __ballot_sync(0xffffffffu, bits == mb);
            int winLane = __ffs(vot) - 1;                  // first lane = first index
            if (lane == winLane) {
                int j = 7;                                  // descending: first j wins
                #pragma unroll
                for (int jj = 6; jj >= 0; jj--) if (d[jj] == m) j = jj;
                float vx = (j==0)?X[0]:(j==1)?X[1]:(j==2)?X[2]:(j==3)?X[3]
                          :(j==4)?X[4]:(j==5)?X[5]:(j==6)?X[6]:X[7];
                float vy = (j==0)?Y[0]:(j==1)?Y[1]:(j==2)?Y[2]:(j==3)?Y[3]
                          :(j==4)?Y[4]:(j==5)?Y[5]:(j==6)?Y[6]:Y[7];
                float vz = (j==0)?Z[0]:(j==1)?Z[1]:(j==2)?Z[2]:(j==3)?Z[3]
                          :(j==4)?Z[4]:(j==5)?Z[5]:(j==6)?Z[6]:Z[7];
                swc[buf + wid] = make_float4(vx, vy, vz, __uint_as_float(mb));
            }
            __syncthreads();
            float4 cnd = swc[buf + lane];                  // slots 16-31 = zero pads
            unsigned cb = __float_as_uint(cnd.w);
            unsigned mh = __reduce_max_sync(0xffffffffu, cb);
            unsigned v2 = __ballot_sync(0xffffffffu, cb == mh);
            int ws = __ffs(v2) - 1;                        // lowest wid = first index
            float4 c = swc[buf + ws];                      // broadcast LDS
            cx = c.x; cy = c.y; cz = c.z;
            if (t < 3) {
                float v = (t==0) ? c.x : (t==1) ? c.y : c.z;
                size_t o = ((size_t)b*SS + it + 1)*3 + t;
                out_newxyz[o] = v;
                g_newxyz[o]   = v;
            }
        }
    } else {
        // ---------------- f1 role: F1 = W0[:,3:67] x features ----------------
        if (blockIdx.x < 19 && t < 256)
            (&g_stats[0][0])[(blockIdx.x - 16)*256 + t] = 0.f;

        float* Wt = pool;          // [64][64]
        float* Fs = pool + 4096;   // [64][128]
        int bid = blockIdx.x - 16;
        int b = bid >> 5, n0 = (bid & 31)*128;
        for (int i = t; i < 4096; i += 512) {
            int o = i >> 6, c = i & 63;
            Wt[c*64 + o] = w0[o*67 + 3 + c];
        }
        const float* fb = feat + (size_t)b*CC*NN + n0;
        for (int f = t; f < 2048; f += 512) {
            int c = f >> 5, j = f & 31;
            *(float4*)&Fs[c*128 + j*4] = *(const float4*)(fb + (size_t)c*NN + j*4);
        }
        __syncthreads();
        int nl = t >> 4, og = t & 15;
        float acc[4][4];
        #pragma unroll
        for (int r = 0; r < 4; r++) {
            #pragma unroll
            for (int o = 0; o < 4; o++) acc[r][o] = 0.f;
        }
        #pragma unroll 8
        for (int c = 0; c < 64; c++) {
            float4 a = *(float4*)&Fs[c*128 + nl*4];
            float4 w = *(float4*)&Wt[c*64 + og*4];
            float av[4] = {a.x, a.y, a.z, a.w};
            float wv[4] = {w.x, w.y, w.z, w.w};
            #pragma unroll
            for (int r = 0; r < 4; r++)
                #pragma unroll
                for (int o = 0; o < 4; o++) acc[r][o] = fmaf(av[r], wv[o], acc[r][o]);
        }
        float* dst = g_F1 + ((size_t)(b*NN + n0 + nl*4))*64 + og*4;
        #pragma unroll
        for (int r = 0; r < 4; r++) {
            float4 x = {acc[r][0], acc[r][1], acc[r][2], acc[r][3]};
            *(float4*)(dst + (size_t)r*64) = x;
        }
    }
}

// ---------------- 2) Ball query: one warp per centroid, early exit ---------
__global__ __launch_bounds__(256) void ball_kernel(const float* __restrict__ xyz)
{
    int gw = blockIdx.x*8 + (threadIdx.x >> 5);
    if (gw >= BB*SS) return;
    int lane = threadIdx.x & 31;
    int b = gw >> 10;
    const float* ctr = g_newxyz + (size_t)gw*3;
    float cx = ctr[0], cy = ctr[1], cz = ctr[2];
    const float* bx = xyz + (size_t)b*NN*3;
    int* out = g_ballidx + (size_t)gw*KK;

    int cnt = 0, first = 0; bool has = false;
    for (int n0 = 0; n0 < NN; n0 += 32) {
        int n = n0 + lane;
        float x = bx[n*3+0], y = bx[n*3+1], z = bx[n*3+2];
        float dx = __fsub_rn(cx, x), dy = __fsub_rn(cy, y), dz = __fsub_rn(cz, z);
        float d2 = __fadd_rn(__fadd_rn(__fmul_rn(dx,dx), __fmul_rn(dy,dy)), __fmul_rn(dz,dz));
        bool in = d2 < 0.04f;
        unsigned bal = __ballot_sync(0xffffffffu, in);
        if (cnt == 0 && bal) { first = n0 + __ffs(bal) - 1; has = true; }
        if (in) {
            int pos = cnt + __popc(bal & ((1u << lane) - 1u));
            if (pos < KK) out[pos] = n;
        }
        cnt += __popc(bal);
        if (cnt >= KK) break;
    }
    if (cnt < KK) {
        int fill = has ? first : 0;
        int p = cnt + lane;
        if (p < KK) out[p] = fill;
    }
}

// --- 3) layer0 assemble: gather F1 + xyz-part + bias, stats, write [c][m] --
//     sF padded to 68 floats/row: float4-aligned gather STS + <=2-way reads.
__global__ __launch_bounds__(256) void assemble_kernel(const float* __restrict__ xyz,
                                                       const float* __restrict__ w0,
                                                       const float* __restrict__ b0)
{
    int m0 = blockIdx.x*128, t = threadIdx.x;
    __shared__ int   sn[128];
    __shared__ float sgx[128], sgy[128], sgz[128];
    __shared__ float sF[128][68];

    if (t < 128) {
        int m = m0 + t; int b = m >> 15; int r = m & 32767; int s = r >> 5;
        int n = g_ballidx[m]; sn[t] = n;
        const float* c = g_newxyz + ((size_t)(b*SS + s))*3;
        const float* p = xyz + ((size_t)(b*NN + n))*3;
        sgx[t] = __fsub_rn(p[0], c[0]);
        sgy[t] = __fsub_rn(p[1], c[1]);
        sgz[t] = __fsub_rn(p[2], c[2]);
    }
    __syncthreads();
    {
        int ml = t >> 1, half = t & 1;
        int m = m0 + ml; int b = m >> 15; int n = sn[ml];
        const float* src = g_F1 + ((size_t)(b*NN + n))*64 + half*32;
        #pragma unroll
        for (int i = 0; i < 8; i++) {
            float4 v = *(const float4*)(src + i*4);
            *(float4*)&sF[ml][half*32 + i*4] = v;   // 16B-aligned (stride 68)
        }
    }
    __syncthreads();
    int o = t >> 2, q = t & 3;
    float wx = w0[o*67+0], wy = w0[o*67+1], wz = w0[o*67+2], bb = b0[o];
    float s1 = 0.f, s2 = 0.f;
    #pragma unroll 8
    for (int i = 0; i < 32; i++) {
        int ml = i*4 + q;
        float v = sF[ml][o] + sgx[ml]*wx + sgy[ml]*wy + sgz[ml]*wz + bb;
        sF[ml][o] = v;
        s1 += v; s2 = fmaf(v, v, s2);
    }
    s1 += __shfl_down_sync(0xffffffffu, s1, 2, 4);
    s1 += __shfl_down_sync(0xffffffffu, s1, 1, 4);
    s2 += __shfl_down_sync(0xffffffffu, s2, 2, 4);
    s2 += __shfl_down_sync(0xffffffffu, s2, 1, 4);
    if (q == 0) {
        atomicAdd(&g_stats[0][o*2],   s1);
        atomicAdd(&g_stats[0][o*2+1], s2);
    }
    __syncthreads();
    int w = t >> 5, lane = t & 31;
    #pragma unroll
    for (int oo = 0; oo < 8; oo++) {
        int o2 = w*8 + oo;
        float4 v = { sF[lane*4+0][o2], sF[lane*4+1][o2], sF[lane*4+2][o2], sF[lane*4+3][o2] };
        *(float4*)(g_y0 + (size_t)o2*MM + m0 + lane*4) = v;
    }
}

// ---------------- BN finalize: scale/shift from stats ----------------------
__global__ void finalize_kernel(const float* __restrict__ g, const float* __restrict__ be,
                                int layer, int cout)
{
    int o = threadIdx.x;
    if (o < cout) {
        float inv  = 1.0f / (float)MM;
        float mean = g_stats[layer][o*2]   * inv;
        float ex2  = g_stats[layer][o*2+1] * inv;
        float var  = fmaxf(ex2 - mean*mean, 0.f);
        float sc   = g[o] * rsqrtf(var + 1e-5f);
        g_scale[layer][o] = sc;
        g_shift[layer][o] = be[o] - sc*mean;
    }
}

// --- 4) GEMM v2c (R11-proven): m256/o64, K 2x32, swizzled Xs, 2 CTAs/SM ----
template<int L, int OT>
__global__ __launch_bounds__(256, 2) void gemm_kernel(const float* __restrict__ W,
                                                      const float* __restrict__ bias)
{
    __shared__ unsigned long long Wd[32][64];   // dup pairs, 16KB (32c x 64o)
    __shared__ float Xs[32][256];               // 32KB (32c x 256m), XOR-swizzled

    const float* X = (L == 1) ? g_y0 : g_y1;
    const int scL = L - 1, stL = L;

    int m0 = blockIdx.x*256, t = threadIdx.x;
    int wid = t >> 5, lane = t & 31;
    int o0 = wid*8;            // warp-uniform o fragment (broadcast LDS)
    int mB = lane*8;           // logical per-lane m fragment (8 floats)
    int off0 = lane*32;        off0 ^= ((off0 >> 3) & 16);
    int off1 = lane*32 + 16;   off1 ^= ((off1 >> 3) & 16);

    for (int ot = 0; ot < OT; ot++) {
        int oB = ot*64;
        unsigned long long acc[8][4];
        #pragma unroll
        for (int o = 0; o < 8; o++) {
            #pragma unroll
            for (int p = 0; p < 4; p++) acc[o][p] = 0ull;
        }

        #pragma unroll
        for (int kc = 0; kc < 64; kc += 32) {
            __syncthreads();
            for (int i = t; i < 2048; i += 256) {
                int c = i >> 6, o = i & 63;
                float w = W[(size_t)(oB + o)*64 + kc + c];
                Wd[c][o] = pack2(w, w);
            }
            for (int f = t; f < 2048; f += 256) {
                int c = f >> 6, j = f & 63;
                float4 v = *(const float4*)(X + (size_t)(kc + c)*MM + m0 + j*4);
                float sc = g_scale[scL][kc + c], sh = g_shift[scL][kc + c];
                v.x = fmaxf(fmaf(v.x, sc, sh), 0.f);
                v.y = fmaxf(fmaf(v.y, sc, sh), 0.f);
                v.z = fmaxf(fmaf(v.z, sc, sh), 0.f);
                v.w = fmaxf(fmaf(v.w, sc, sh), 0.f);
                int joff = j*16; joff ^= ((joff >> 3) & 16);
                *(float4*)((char*)&Xs[c][0] + joff) = v;
            }
            __syncthreads();

            #pragma unroll 2
            for (int c = 0; c < 32; c++) {
                const char* rowp = (const char*)&Xs[c][0];
                ulonglong2 b0 = *(const ulonglong2*)(rowp + off0);
                ulonglong2 b1 = *(const ulonglong2*)(rowp + off1);
                unsigned long long bp[4] = {b0.x, b0.y, b1.x, b1.y};
                ulonglong2 a0 = *(const ulonglong2*)&Wd[c][o0];
                ulonglong2 a1 = *(const ulonglong2*)&Wd[c][o0+2];
                ulonglong2 a2 = *(const ulonglong2*)&Wd[c][o0+4];
                ulonglong2 a3 = *(const ulonglong2*)&Wd[c][o0+6];
                unsigned long long ad[8] = {a0.x, a0.y, a1.x, a1.y,
                                            a2.x, a2.y, a3.x, a3.y};
                #pragma unroll
                for (int o = 0; o < 8; o++)
                    #pragma unroll
                    for (int p = 0; p < 4; p++)
                        acc[o][p] = fma2(ad[o], bp[p], acc[o][p]);
            }
        }

        #pragma unroll
        for (int o = 0; o < 8; o++) {
            int og = oB + o0 + o;
            float bb = bias[og];
            float v[8];
            #pragma unroll
            for (int p = 0; p < 4; p++) {
                float lo, hi; unpack2(lo, hi, acc[o][p]);
                v[2*p]   = lo + bb;
                v[2*p+1] = hi + bb;
            }
            if (L == 1) {
                float4 f0 = {v[0], v[1], v[2], v[3]};
                float4 f1 = {v[4], v[5], v[6], v[7]};
                float* dst = g_y1 + (size_t)og*MM + m0 + mB;
                *(float4*)dst       = f0;
                *(float4*)(dst + 4) = f1;
            } else {
                float mx = v[0], mn = v[0];
                #pragma unroll
                for (int i = 1; i < 8; i++) { mx = fmaxf(mx, v[i]); mn = fminf(mn, v[i]); }
                mx = fmaxf(mx, __shfl_down_sync(0xffffffffu, mx, 2, 4));
                mx = fmaxf(mx, __shfl_down_sync(0xffffffffu, mx, 1, 4));
                mn = fminf(mn, __shfl_down_sync(0xffffffffu, mn, 2, 4));
                mn = fminf(mn, __shfl_down_sync(0xffffffffu, mn, 1, 4));
                if ((lane & 3) == 0) {
                    int sg = (m0 >> 5) + (lane >> 2);   // global (b*SS+s)
                    g_pmax[(size_t)og*16384 + sg] = mx;
                    g_pmin[(size_t)og*16384 + sg] = mn;
                }
            }
            float s1 = v[0]+v[1]+v[2]+v[3]+v[4]+v[5]+v[6]+v[7];
            float s2 = v[0]*v[0]+v[1]*v[1]+v[2]*v[2]+v[3]*v[3]
                     + v[4]*v[4]+v[5]*v[5]+v[6]*v[6]+v[7]*v[7];
            #pragma unroll
            for (int off = 16; off; off >>= 1) {
                s1 += __shfl_down_sync(0xffffffffu, s1, off);
                s2 += __shfl_down_sync(0xffffffffu, s2, off);
            }
            if (lane == 0) {
                atomicAdd(&g_stats[stL][og*2],   s1);
                atomicAdd(&g_stats[stL][og*2+1], s2);
            }
        }
    }
}

// --- 5) final: BN2 finalize inline; out = max(relu(a*mx+b), relu(a*mn+b)) --
__global__ __launch_bounds__(256) void out_kernel(const float* __restrict__ g2,
                                                  const float* __restrict__ be2,
                                                  float* __restrict__ out)
{
    int id = blockIdx.x*256 + threadIdx.x;     // < 128*16384
    int o = id >> 14, sg = id & 16383;
    int b = sg >> 10, s = sg & 1023;
    float inv  = 1.0f / (float)MM;
    float mean = g_stats[2][o*2]   * inv;
    float ex2  = g_stats[2][o*2+1] * inv;
    float var  = fmaxf(ex2 - mean*mean, 0.f);
    float a    = g2[o] * rsqrtf(var + 1e-5f);
    float sh   = be2[o] - a*mean;
    float mx = g_pmax[(size_t)o*16384 + sg];
    float mn = g_pmin[(size_t)o*16384 + sg];
    float v1 = fmaxf(fmaf(mx, a, sh), 0.f);
    float v2 = fmaxf(fmaf(mn, a, sh), 0.f);
    out[((size_t)(b*128 + o))*SS + s] = fmaxf(v1, v2);
}

// ---------------------------------------------------------------------------
extern "C" void kernel_launch(void* const* d_in, const int* in_sizes, int n_in,
                              void* d_out, int out_size)
{
    const float* xyz  = (const float*)d_in[0];
    const float* feat = (const float*)d_in[1];
    const float* w0   = (const float*)d_in[2];
    const float* b0   = (const float*)d_in[3];
    const float* g0   = (const float*)d_in[4];
    const float* be0  = (const float*)d_in[5];
    const float* w1   = (const float*)d_in[6];
    const float* b1   = (const float*)d_in[7];
    const float* g1   = (const float*)d_in[8];
    const float* be1  = (const float*)d_in[9];
    const float* w2   = (const float*)d_in[10];
    const float* b2   = (const float*)d_in[11];
    const float* g2   = (const float*)d_in[12];
    const float* be2  = (const float*)d_in[13];
    float* out = (float*)d_out;

    fps_f1_kernel<<<528, 512>>>(xyz, feat, w0, out);          // 1: new_xyz + F1 + stat zero
    ball_kernel<<<2048, 256>>>(xyz);                          // 2
    assemble_kernel<<<4096, 256>>>(xyz, w0, b0);              // 3: y0 + stats0
    finalize_kernel<<<1, 128>>>(g0, be0, 0, 64);              // 4
    gemm_kernel<1,1><<<2048, 256>>>(w1, b1);                  // 5: y1 + stats1
    finalize_kernel<<<1, 128>>>(g1, be1, 1, 64);              // 6
    gemm_kernel<2,2><<<2048, 256>>>(w2, b2);                  // 7: pool + stats2
    out_kernel<<<8192, 256>>>(g2, be2, out + (size_t)BB*SS*3);// 8: new_features
}

// round 16
// speedup vs baseline: 3.7928x; 1.0037x over previous
#include <cuda_runtime.h>
#include <cstdint>

#define BB 16
#define NN 4096
#define CC 64
#define SS 1024
#define KK 32
#define MM (BB*SS*KK)   /* 524288 */

// ---------------- scratch (device globals; no runtime allocation) ----------
__device__ float g_newxyz[BB*SS*3];
__device__ int   g_ballidx[MM];
__device__ float g_F1[BB*NN*64];              // [b][n][o], o contiguous (16.7 MB)
__device__ float g_y0[(size_t)64*MM];         // pre-BN layer0 out [c][m]
__device__ float g_y1[(size_t)64*MM];         // pre-BN layer1 out
__device__ float g_pmax[(size_t)128*16384];   // layer2 pre-BN max over k, [o][b*s]
__device__ float g_pmin[(size_t)128*16384];   // layer2 pre-BN min over k
__device__ float g_stats[3][256];             // per layer: [ch*2]={sum,sumsq}
__device__ float g_scale[3][128];
__device__ float g_shift[3][128];

// packed f32x2 helpers (bitwise identical to scalar rn ops, 2 lanes/instr)
__device__ __forceinline__ unsigned long long fma2(unsigned long long a,
                                                   unsigned long long b,
                                                   unsigned long long c)
{
    unsigned long long d;
    asm("fma.rn.f32x2 %0, %1, %2, %3;" : "=l"(d) : "l"(a), "l"(b), "l"(c));
    return d;
}
__device__ __forceinline__ unsigned long long add2(unsigned long long a,
                                                   unsigned long long b)
{
    unsigned long long d;
    asm("add.rn.f32x2 %0, %1, %2;" : "=l"(d) : "l"(a), "l"(b));
    return d;
}
__device__ __forceinline__ unsigned long long mul2(unsigned long long a,
                                                   unsigned long long b)
{
    unsigned long long d;
    asm("mul.rn.f32x2 %0, %1, %2;" : "=l"(d) : "l"(a), "l"(b));
    return d;
}
__device__ __forceinline__ unsigned long long pack2(float lo, float hi)
{
    unsigned long long d;
    asm("mov.b64 %0, {%1, %2};" : "=l"(d) : "f"(lo), "f"(hi));
    return d;
}
__device__ __forceinline__ void unpack2(float& lo, float& hi, unsigned long long v)
{
    asm("mov.b64 {%0, %1}, %2;" : "=f"(lo), "=f"(hi) : "l"(v));
}

// ---- 1) merged: blocks 0..15 = FPS (512thr x 8pts), 16..527 = f1 GEMM -----
//      blocks 16..18 additionally zero g_stats.
__global__ __launch_bounds__(512) void fps_f1_kernel(const float* __restrict__ xyz,
                                                     const float* __restrict__ feat,
                                                     const float* __restrict__ w0,
                                                     float* __restrict__ out_newxyz)
{
    __shared__ float pool[12288];   // 48KB, shared by both roles
    int t = threadIdx.x;

    if (blockIdx.x < 16) {
        // ---------------- FPS role ----------------
        float4* swc = (float4*)pool;            // [2][32] {x,y,z,keybits}
        int b = blockIdx.x;
        int lane = t & 31, wid = t >> 5;        // wid 0..15
        if (t < 64) swc[t] = make_float4(0.f, 0.f, 0.f, 0.f);  // pads zeroed

        const float* xb = xyz + (size_t)b*NN*3;
        const float4* p = (const float4*)xb + t*6;
        float4 q0=p[0], q1=p[1], q2=p[2], q3=p[3], q4=p[4], q5=p[5];
        float X[8], Y[8], Z[8];
        X[0]=q0.x; Y[0]=q0.y; Z[0]=q0.z;
        X[1]=q0.w; Y[1]=q1.x; Z[1]=q1.y;
        X[2]=q1.z; Y[2]=q1.w; Z[2]=q2.x;
        X[3]=q2.y; Y[3]=q2.z; Z[3]=q2.w;
        X[4]=q3.x; Y[4]=q3.y; Z[4]=q3.z;
        X[5]=q3.w; Y[5]=q4.x; Z[5]=q4.y;
        X[6]=q4.z; Y[6]=q4.w; Z[6]=q5.x;
        X[7]=q5.y; Y[7]=q5.z; Z[7]=q5.w;
        unsigned long long pxP[4], pyP[4], pzP[4];
        #pragma unroll
        for (int g = 0; g < 4; g++) {
            pxP[g] = pack2(X[2*g], X[2*g+1]);
            pyP[g] = pack2(Y[2*g], Y[2*g+1]);
            pzP[g] = pack2(Z[2*g], Z[2*g+1]);
        }
        float d[8];
        #pragma unroll
        for (int j = 0; j < 8; j++) d[j] = 1e10f;

        float cx = xb[0], cy = xb[1], cz = xb[2];
        if (t == 0) {
            float* o  = out_newxyz + (size_t)b*SS*3;
            float* o2 = g_newxyz  + (size_t)b*SS*3;
            o[0]=cx; o[1]=cy; o[2]=cz;
            o2[0]=cx; o2[1]=cy; o2[2]=cz;
        }
        __syncthreads();

        for (int it = 0; it < SS-1; ++it) {
            int buf = (it & 1)*32;
            unsigned long long nx = pack2(-cx,-cx);
            unsigned long long ny = pack2(-cy,-cy);
            unsigned long long nz = pack2(-cz,-cz);
            #pragma unroll
            for (int g = 0; g < 4; g++) {
                unsigned long long dx = add2(pxP[g], nx);
                unsigned long long dy = add2(pyP[g], ny);
                unsigned long long dz = add2(pzP[g], nz);
                unsigned long long s  = add2(add2(mul2(dx,dx), mul2(dy,dy)), mul2(dz,dz));
                float e0, e1; unpack2(e0, e1, s);
                d[2*g]   = fminf(d[2*g],   e0);
                d[2*g+1] = fminf(d[2*g+1], e1);
            }
            float m = d[0];
            #pragma unroll
            for (int j = 1; j < 8; j++) m = fmaxf(m, d[j]);
            unsigned bits = __float_as_uint(m);            // d >= 0: order-preserving
            unsigned mb = __reduce_max_sync(0xffffffffu, bits);
            unsigned vot = __ballot_sync(0xffffffffu, bits == mb);
            int winLane = __ffs(vot) - 1;                  // first lane = first index
            if (lane == winLane) {
                int j = 7;                                  // descending: first j wins
                #pragma unroll
                for (int jj = 6; jj >= 0; jj--) if (d[jj] == m) j = jj;
                float vx = (j==0)?X[0]:(j==1)?X[1]:(j==2)?X[2]:(j==3)?X[3]
                          :(j==4)?X[4]:(j==5)?X[5]:(j==6)?X[6]:X[7];
                float vy = (j==0)?Y[0]:(j==1)?Y[1]:(j==2)?Y[2]:(j==3)?Y[3]
                          :(j==4)?Y[4]:(j==5)?Y[5]:(j==6)?Y[6]:Y[7];
                float vz = (j==0)?Z[0]:(j==1)?Z[1]:(j==2)?Z[2]:(j==3)?Z[3]
                          :(j==4)?Z[4]:(j==5)?Z[5]:(j==6)?Z[6]:Z[7];
                swc[buf + wid] = make_float4(vx, vy, vz, __uint_as_float(mb));
            }
            __syncthreads();
            float4 cnd = swc[buf + lane];                  // slots 16-31 = zero pads
            unsigned cb = __float_as_uint(cnd.w);
            unsigned mh = __reduce_max_sync(0xffffffffu, cb);
            unsigned v2 = __ballot_sync(0xffffffffu, cb == mh);
            int ws = __ffs(v2) - 1;                        // lowest wid = first index
            float4 c = swc[buf + ws];                      // broadcast LDS
            cx = c.x; cy = c.y; cz = c.z;
            if (t < 3) {
                float v = (t==0) ? c.x : (t==1) ? c.y : c.z;
                size_t o = ((size_t)b*SS + it + 1)*3 + t;
                out_newxyz[o] = v;
                g_newxyz[o]   = v;
            }
        }
    } else {
        // ---------------- f1 role: F1 = W0[:,3:67] x features ----------------
        if (blockIdx.x < 19 && t < 256)
            (&g_stats[0][0])[(blockIdx.x - 16)*256 + t] = 0.f;

        float* Wt = pool;          // [64][64]
        float* Fs = pool + 4096;   // [64][128]
        int bid = blockIdx.x - 16;
        int b = bid >> 5, n0 = (bid & 31)*128;
        for (int i = t; i < 4096; i += 512) {
            int o = i >> 6, c = i & 63;
            Wt[c*64 + o] = w0[o*67 + 3 + c];
        }
        const float* fb = feat + (size_t)b*CC*NN + n0;
        for (int f = t; f < 2048; f += 512) {
            int c = f >> 5, j = f & 31;
            *(float4*)&Fs[c*128 + j*4] = *(const float4*)(fb + (size_t)c*NN + j*4);
        }
        __syncthreads();
        int nl = t >> 4, og = t & 15;
        float acc[4][4];
        #pragma unroll
        for (int r = 0; r < 4; r++) {
            #pragma unroll
            for (int o = 0; o < 4; o++) acc[r][o] = 0.f;
        }
        #pragma unroll 8
        for (int c = 0; c < 64; c++) {
            float4 a = *(float4*)&Fs[c*128 + nl*4];
            float4 w = *(float4*)&Wt[c*64 + og*4];
            float av[4] = {a.x, a.y, a.z, a.w};
            float wv[4] = {w.x, w.y, w.z, w.w};
            #pragma unroll
            for (int r = 0; r < 4; r++)
                #pragma unroll
                for (int o = 0; o < 4; o++) acc[r][o] = fmaf(av[r], wv[o], acc[r][o]);
        }
        float* dst = g_F1 + ((size_t)(b*NN + n0 + nl*4))*64 + og*4;
        #pragma unroll
        for (int r = 0; r < 4; r++) {
            float4 x = {acc[r][0], acc[r][1], acc[r][2], acc[r][3]};
            *(float4*)(dst + (size_t)r*64) = x;
        }
    }
}

// ---------------- 2) Ball query: one warp per centroid, early exit ---------
__global__ __launch_bounds__(256) void ball_kernel(const float* __restrict__ xyz)
{
    int gw = blockIdx.x*8 + (threadIdx.x >> 5);
    if (gw >= BB*SS) return;
    int lane = threadIdx.x & 31;
    int b = gw >> 10;
    const float* ctr = g_newxyz + (size_t)gw*3;
    float cx = ctr[0], cy = ctr[1], cz = ctr[2];
    const float* bx = xyz + (size_t)b*NN*3;
    int* out = g_ballidx + (size_t)gw*KK;

    int cnt = 0, first = 0; bool has = false;
    for (int n0 = 0; n0 < NN; n0 += 32) {
        int n = n0 + lane;
        float x = bx[n*3+0], y = bx[n*3+1], z = bx[n*3+2];
        float dx = __fsub_rn(cx, x), dy = __fsub_rn(cy, y), dz = __fsub_rn(cz, z);
        float d2 = __fadd_rn(__fadd_rn(__fmul_rn(dx,dx), __fmul_rn(dy,dy)), __fmul_rn(dz,dz));
        bool in = d2 < 0.04f;
        unsigned bal = __ballot_sync(0xffffffffu, in);
        if (cnt == 0 && bal) { first = n0 + __ffs(bal) - 1; has = true; }
        if (in) {
            int pos = cnt + __popc(bal & ((1u << lane) - 1u));
            if (pos < KK) out[pos] = n;
        }
        cnt += __popc(bal);
        if (cnt >= KK) break;
    }
    if (cnt < KK) {
        int fill = has ? first : 0;
        int p = cnt + lane;
        if (p < KK) out[p] = fill;
    }
}

// --- 3) layer0 assemble: gather F1 + xyz-part + bias, stats, write [c][m] --
__global__ __launch_bounds__(256) void assemble_kernel(const float* __restrict__ xyz,
                                                       const float* __restrict__ w0,
                                                       const float* __restrict__ b0)
{
    int m0 = blockIdx.x*128, t = threadIdx.x;
    __shared__ int   sn[128];
    __shared__ float sgx[128], sgy[128], sgz[128];
    __shared__ float sF[128][68];

    if (t < 128) {
        int m = m0 + t; int b = m >> 15; int r = m & 32767; int s = r >> 5;
        int n = g_ballidx[m]; sn[t] = n;
        const float* c = g_newxyz + ((size_t)(b*SS + s))*3;
        const float* p = xyz + ((size_t)(b*NN + n))*3;
        sgx[t] = __fsub_rn(p[0], c[0]);
        sgy[t] = __fsub_rn(p[1], c[1]);
        sgz[t] = __fsub_rn(p[2], c[2]);
    }
    __syncthreads();
    {
        int ml = t >> 1, half = t & 1;
        int m = m0 + ml; int b = m >> 15; int n = sn[ml];
        const float* src = g_F1 + ((size_t)(b*NN + n))*64 + half*32;
        #pragma unroll
        for (int i = 0; i < 8; i++) {
            float4 v = *(const float4*)(src + i*4);
            *(float4*)&sF[ml][half*32 + i*4] = v;   // 16B-aligned (stride 68)
        }
    }
    __syncthreads();
    int o = t >> 2, q = t & 3;
    float wx = w0[o*67+0], wy = w0[o*67+1], wz = w0[o*67+2], bb = b0[o];
    float s1 = 0.f, s2 = 0.f;
    #pragma unroll 8
    for (int i = 0; i < 32; i++) {
        int ml = i*4 + q;
        float v = sF[ml][o] + sgx[ml]*wx + sgy[ml]*wy + sgz[ml]*wz + bb;
        sF[ml][o] = v;
        s1 += v; s2 = fmaf(v, v, s2);
    }
    s1 += __shfl_down_sync(0xffffffffu, s1, 2, 4);
    s1 += __shfl_down_sync(0xffffffffu, s1, 1, 4);
    s2 += __shfl_down_sync(0xffffffffu, s2, 2, 4);
    s2 += __shfl_down_sync(0xffffffffu, s2, 1, 4);
    if (q == 0) {
        atomicAdd(&g_stats[0][o*2],   s1);
        atomicAdd(&g_stats[0][o*2+1], s2);
    }
    __syncthreads();
    int w = t >> 5, lane = t & 31;
    #pragma unroll
    for (int oo = 0; oo < 8; oo++) {
        int o2 = w*8 + oo;
        float4 v = { sF[lane*4+0][o2], sF[lane*4+1][o2], sF[lane*4+2][o2], sF[lane*4+3][o2] };
        *(float4*)(g_y0 + (size_t)o2*MM + m0 + lane*4) = v;
    }
}

// ---------------- BN finalize: scale/shift from stats ----------------------
__global__ void finalize_kernel(const float* __restrict__ g, const float* __restrict__ be,
                                int layer, int cout)
{
    int o = threadIdx.x;
    if (o < cout) {
        float inv  = 1.0f / (float)MM;
        float mean = g_stats[layer][o*2]   * inv;
        float ex2  = g_stats[layer][o*2+1] * inv;
        float var  = fmaxf(ex2 - mean*mean, 0.f);
        float sc   = g[o] * rsqrtf(var + 1e-5f);
        g_scale[layer][o] = sc;
        g_shift[layer][o] = be[o] - sc*mean;
    }
}

// --- 4) GEMM v2d: m256/o64, K 2x32, swizzled Xs, 2 CTAs/SM.
//     o-tile on blockIdx.x (fastest) so same-m blocks pair in L2.
template<int L>
__global__ __launch_bounds__(256, 2) void gemm_kernel(const float* __restrict__ W,
                                                      const float* __restrict__ bias)
{
    __shared__ unsigned long long Wd[32][64];   // dup pairs, 16KB (32c x 64o)
    __shared__ float Xs[32][256];               // 32KB (32c x 256m), XOR-swizzled

    const float* X = (L == 1) ? g_y0 : g_y1;
    const int scL = L - 1, stL = L;

    int m0 = blockIdx.y*256, oB = blockIdx.x*64, t = threadIdx.x;
    int wid = t >> 5, lane = t & 31;
    int o0 = wid*8;            // warp-uniform o fragment (broadcast LDS)
    int mB = lane*8;           // logical per-lane m fragment (8 floats)
    int off0 = lane*32;        off0 ^= ((off0 >> 3) & 16);
    int off1 = lane*32 + 16;   off1 ^= ((off1 >> 3) & 16);

    unsigned long long acc[8][4];
    #pragma unroll
    for (int o = 0; o < 8; o++) {
        #pragma unroll
        for (int p = 0; p < 4; p++) acc[o][p] = 0ull;
    }

    #pragma unroll
    for (int kc = 0; kc < 64; kc += 32) {
        __syncthreads();
        for (int i = t; i < 2048; i += 256) {
            int c = i >> 6, o = i & 63;
            float w = W[(size_t)(oB + o)*64 + kc + c];
            Wd[c][o] = pack2(w, w);
        }
        for (int f = t; f < 2048; f += 256) {
            int c = f >> 6, j = f & 63;
            float4 v = *(const float4*)(X + (size_t)(kc + c)*MM + m0 + j*4);
            float sc = g_scale[scL][kc + c], sh = g_shift[scL][kc + c];
            v.x = fmaxf(fmaf(v.x, sc, sh), 0.f);
            v.y = fmaxf(fmaf(v.y, sc, sh), 0.f);
            v.z = fmaxf(fmaf(v.z, sc, sh), 0.f);
            v.w = fmaxf(fmaf(v.w, sc, sh), 0.f);
            int joff = j*16; joff ^= ((joff >> 3) & 16);
            *(float4*)((char*)&Xs[c][0] + joff) = v;
        }
        __syncthreads();

        #pragma unroll 2
        for (int c = 0; c < 32; c++) {
            const char* rowp = (const char*)&Xs[c][0];
            ulonglong2 b0 = *(const ulonglong2*)(rowp + off0);
            ulonglong2 b1 = *(const ulonglong2*)(rowp + off1);
            unsigned long long bp[4] = {b0.x, b0.y, b1.x, b1.y};
            ulonglong2 a0 = *(const ulonglong2*)&Wd[c][o0];
            ulonglong2 a1 = *(const ulonglong2*)&Wd[c][o0+2];
            ulonglong2 a2 = *(const ulonglong2*)&Wd[c][o0+4];
            ulonglong2 a3 = *(const ulonglong2*)&Wd[c][o0+6];
            unsigned long long ad[8] = {a0.x, a0.y, a1.x, a1.y,
                                        a2.x, a2.y, a3.x, a3.y};
            #pragma unroll
            for (int o = 0; o < 8; o++)
                #pragma unroll
                for (int p = 0; p < 4; p++)
                    acc[o][p] = fma2(ad[o], bp[p], acc[o][p]);
        }
    }

    #pragma unroll
    for (int o = 0; o < 8; o++) {
        int og = oB + o0 + o;
        float bb = bias[og];
        float v[8];
        #pragma unroll
        for (int p = 0; p < 4; p++) {
            float lo, hi; unpack2(lo, hi, acc[o][p]);
            v[2*p]   = lo + bb;
            v[2*p+1] = hi + bb;
        }
        if (L == 1) {
            float4 f0 = {v[0], v[1], v[2], v[3]};
            float4 f1 = {v[4], v[5], v[6], v[7]};
            float* dst = g_y1 + (size_t)og*MM + m0 + mB;
            *(float4*)dst       = f0;
            *(float4*)(dst + 4) = f1;
        } else {
            float mx = v[0], mn = v[0];
            #pragma unroll
            for (int i = 1; i < 8; i++) { mx = fmaxf(mx, v[i]); mn = fminf(mn, v[i]); }
            mx = fmaxf(mx, __shfl_down_sync(0xffffffffu, mx, 2, 4));
            mx = fmaxf(mx, __shfl_down_sync(0xffffffffu, mx, 1, 4));
            mn = fminf(mn, __shfl_down_sync(0xffffffffu, mn, 2, 4));
            mn = fminf(mn, __shfl_down_sync(0xffffffffu, mn, 1, 4));
            if ((lane & 3) == 0) {
                int sg = (m0 >> 5) + (lane >> 2);   // global (b*SS+s)
                g_pmax[(size_t)og*16384 + sg] = mx;
                g_pmin[(size_t)og*16384 + sg] = mn;
            }
        }
        float s1 = v[0]+v[1]+v[2]+v[3]+v[4]+v[5]+v[6]+v[7];
        float s2 = v[0]*v[0]+v[1]*v[1]+v[2]*v[2]+v[3]*v[3]
                 + v[4]*v[4]+v[5]*v[5]+v[6]*v[6]+v[7]*v[7];
        #pragma unroll
        for (int off = 16; off; off >>= 1) {
            s1 += __shfl_down_sync(0xffffffffu, s1, off);
            s2 += __shfl_down_sync(0xffffffffu, s2, off);
        }
        if (lane == 0) {
            atomicAdd(&g_stats[stL][og*2],   s1);
            atomicAdd(&g_stats[stL][og*2+1], s2);
        }
    }
}

// --- 5) final: BN2 finalize inline; out = max(relu(a*mx+b), relu(a*mn+b)) --
__global__ __launch_bounds__(256) void out_kernel(const float* __restrict__ g2,
                                                  const float* __restrict__ be2,
                                                  float* __restrict__ out)
{
    int id = blockIdx.x*256 + threadIdx.x;     // < 128*16384
    int o = id >> 14, sg = id & 16383;
    int b = sg >> 10, s = sg & 1023;
    float inv  = 1.0f / (float)MM;
    float mean = g_stats[2][o*2]   * inv;
    float ex2  = g_stats[2][o*2+1] * inv;
    float var  = fmaxf(ex2 - mean*mean, 0.f);
    float a    = g2[o] * rsqrtf(var + 1e-5f);
    float sh   = be2[o] - a*mean;
    float mx = g_pmax[(size_t)o*16384 + sg];
    float mn = g_pmin[(size_t)o*16384 + sg];
    float v1 = fmaxf(fmaf(mx, a, sh), 0.f);
    float v2 = fmaxf(fmaf(mn, a, sh), 0.f);
    out[((size_t)(b*128 + o))*SS + s] = fmaxf(v1, v2);
}

// ---------------------------------------------------------------------------
extern "C" void kernel_launch(void* const* d_in, const int* in_sizes, int n_in,
                              void* d_out, int out_size)
{
    const float* xyz  = (const float*)d_in[0];
    const float* feat = (const float*)d_in[1];
    const float* w0   = (const float*)d_in[2];
    const float* b0   = (const float*)d_in[3];
    const float* g0   = (const float*)d_in[4];
    const float* be0  = (const float*)d_in[5];
    const float* w1   = (const float*)d_in[6];
    const float* b1   = (const float*)d_in[7];
    const float* g1   = (const float*)d_in[8];
    const float* be1  = (const float*)d_in[9];
    const float* w2   = (const float*)d_in[10];
    const float* b2   = (const float*)d_in[11];
    const float* g2   = (const float*)d_in[12];
    const float* be2  = (const float*)d_in[13];
    float* out = (float*)d_out;

    fps_f1_kernel<<<528, 512>>>(xyz, feat, w0, out);          // 1: new_xyz + F1 + stat zero
    ball_kernel<<<2048, 256>>>(xyz);                          // 2
    assemble_kernel<<<4096, 256>>>(xyz, w0, b0);              // 3: y0 + stats0
    finalize_kernel<<<1, 128>>>(g0, be0, 0, 64);              // 4
    gemm_kernel<1><<<dim3(1, 2048), 256>>>(w1, b1);           // 5: y1 + stats1
    finalize_kernel<<<1, 128>>>(g1, be1, 1, 64);              // 6
    gemm_kernel<2><<<dim3(2, 2048), 256>>>(w2, b2);           // 7: pool + stats2 (L2-paired)
    out_kernel<<<8192, 256>>>(g2, be2, out + (size_t)BB*SS*3);// 8: new_features
}